// round 7
// baseline (speedup 1.0000x reference)
#include <cuda_runtime.h>
#include <math.h>

#define NN 100000
#define EE 3200000

// ---------------- scratch (static __device__ globals: no allocs allowed) ----
__device__ float  g_h2[512];
__device__ float  g_deg[NN];
__device__ float  g_dinv[NN];
__device__ float2 g_ms1[NN];     // m1 * dinv  (gather side of conv1)
__device__ float2 g_agg1[NN];    // conv1 accumulator (init = self-loop term)
__device__ float  g_ms2[NN];     // m2 * dinv
__device__ float  g_agg2[NN];    // conv2 accumulator
__device__ int    g_src[EE];
__device__ int    g_dst[EE];
__device__ int    g_is64;

// ---------------- dtype detection: int64 vs int32 edge_index ---------------
// If buffer is int32, an int64 view of entry i is a + b*2^32 (b = next index,
// ~never 0 for 32 consecutive entries). If genuinely int64, all values < NN.
__global__ void k_detect(const long long* __restrict__ ei) {
    int ok = 1;
    for (int i = 0; i < 32; i++) {
        long long v = ei[i];
        if (v < 0 || v >= NN) { ok = 0; break; }
    }
    g_is64 = ok;
}

// ---------------- tiny MLP front: h2 = relu(relu(x@W1+b1)@W2+b2) -----------
// grid=4, block=256. Each block redundantly computes h1 (cheap, 128KB W1),
// then computes 128 h2 outputs with 2-way split-k for latency hiding.
__global__ void k_mlp_front(const float* __restrict__ x,
                            const float* __restrict__ W1,
                            const float* __restrict__ b1,
                            const float* __restrict__ W2,
                            const float* __restrict__ b2) {
    __shared__ float sx[128];
    __shared__ float sh1[256];
    __shared__ float red[256];
    int t = threadIdx.x;
    if (t < 128) sx[t] = x[t];
    __syncthreads();

    float acc = 0.f;
    #pragma unroll 8
    for (int k = 0; k < 128; k++) acc = fmaf(sx[k], W1[k * 256 + t], acc);
    sh1[t] = fmaxf(acc + b1[t], 0.f);
    __syncthreads();

    int j = blockIdx.x * 128 + (t & 127);
    int slice = t >> 7;              // 0 or 1
    float a2 = 0.f;
    int k0 = slice * 128;
    #pragma unroll 8
    for (int k = k0; k < k0 + 128; k++) a2 = fmaf(sh1[k], W2[k * 512 + j], a2);
    red[t] = a2;
    __syncthreads();
    if (slice == 0) {
        g_h2[j] = fmaxf(red[t] + red[t + 128] + b2[j], 0.f);
    }
}

// ---------------- degree init ----------------------------------------------
__global__ void k_deg_init() {
    int n = blockIdx.x * blockDim.x + threadIdx.x;
    if (n < NN) g_deg[n] = 1.0f;   // +1 self-loop
}

// ---------------- edge prep: unpack indices to int32 + degree scatter ------
__global__ void k_prep_edges(const void* __restrict__ ei, int E) {
    int e = blockIdx.x * blockDim.x + threadIdx.x;
    if (e >= E) return;
    int s, d;
    if (g_is64) {
        const long long* p = (const long long*)ei;
        s = (int)p[e];
        d = (int)p[E + e];
    } else {
        const int* p = (const int*)ei;
        s = p[e];
        d = p[E + e];
    }
    g_src[e] = s;
    g_dst[e] = d;
    atomicAdd(&g_deg[d], 1.0f);
}

// ---------------- dinv = deg^-1/2 ------------------------------------------
__global__ void k_dinv() {
    int n = blockIdx.x * blockDim.x + threadIdx.x;
    if (n < NN) g_dinv[n] = rsqrtf(g_deg[n]);
}

// ---------------- BIG GEMV: h = relu(h2 @ W3 + b3), fused conv1 prologue ---
// One thread per node n: float4 over the 4 features (cols 4n..4n+3).
// W3 row-major [512, 400000] -> float4 index k*100000 + n (coalesced).
__global__ void k_gemv(const float4* __restrict__ W3,
                       const float4* __restrict__ b3,
                       const float*  __restrict__ Wg1) {
    __shared__ float sh2[512];
    __shared__ float swg[8];
    int t = threadIdx.x;
    for (int i = t; i < 512; i += 256) sh2[i] = g_h2[i];
    if (t < 8) swg[t] = Wg1[t];
    __syncthreads();

    int n = blockIdx.x * 256 + t;
    if (n >= NN) return;

    float4 acc = b3[n];
    const float4* Wp = W3 + n;
    #pragma unroll 8
    for (int k = 0; k < 512; k++) {
        float4 w = Wp[k * 100000];
        float  h = sh2[k];
        acc.x = fmaf(h, w.x, acc.x);
        acc.y = fmaf(h, w.y, acc.y);
        acc.z = fmaf(h, w.z, acc.z);
        acc.w = fmaf(h, w.w, acc.w);
    }
    float h0 = fmaxf(acc.x, 0.f);
    float h1 = fmaxf(acc.y, 0.f);
    float h2 = fmaxf(acc.z, 0.f);
    float h3 = fmaxf(acc.w, 0.f);

    // m1 = h @ Wg1   (Wg1 row-major [4,2])
    float m0 = h0 * swg[0] + h1 * swg[2] + h2 * swg[4] + h3 * swg[6];
    float m1 = h0 * swg[1] + h1 * swg[3] + h2 * swg[5] + h3 * swg[7];

    float di = g_dinv[n];
    g_ms1[n]  = make_float2(m0 * di, m1 * di);
    g_agg1[n] = make_float2(m0 * di * di, m1 * di * di);   // self-loop: m/deg
}

// ---------------- conv1 edge scatter (vector RED, sm_90+) ------------------
__global__ void k_edge1(int E) {
    int e = blockIdx.x * blockDim.x + threadIdx.x;
    if (e >= E) return;
    int s = g_src[e], d = g_dst[e];
    float  nd = g_dinv[d];
    float2 ms = g_ms1[s];
    float2* p = &g_agg1[d];
    asm volatile("red.global.add.v2.f32 [%0], {%1, %2};"
                 :: "l"(p), "f"(ms.x * nd), "f"(ms.y * nd) : "memory");
}

// ---------------- conv1 epilogue + conv2 prologue --------------------------
__global__ void k_node2(const float* __restrict__ bg1,
                        const float* __restrict__ Wg2) {
    int n = blockIdx.x * blockDim.x + threadIdx.x;
    if (n >= NN) return;
    float2 a = g_agg1[n];
    float z0 = fmaxf(a.x + bg1[0], 0.f);
    float z1 = fmaxf(a.y + bg1[1], 0.f);
    float m2 = z0 * Wg2[0] + z1 * Wg2[1];
    float di = g_dinv[n];
    g_ms2[n]  = m2 * di;
    g_agg2[n] = m2 * di * di;     // self-loop term
}

// ---------------- conv2 edge scatter ---------------------------------------
__global__ void k_edge2(int E) {
    int e = blockIdx.x * blockDim.x + threadIdx.x;
    if (e >= E) return;
    int s = g_src[e], d = g_dst[e];
    atomicAdd(&g_agg2[d], g_ms2[s] * g_dinv[d]);
}

// ---------------- output: sigmoid ------------------------------------------
__global__ void k_out(float* __restrict__ out, const float* __restrict__ bg2) {
    int n = blockIdx.x * blockDim.x + threadIdx.x;
    if (n >= NN) return;
    float v = g_agg2[n] + bg2[0];
    out[n] = 1.0f / (1.0f + expf(-v));
}

// ---------------- launch ----------------------------------------------------
extern "C" void kernel_launch(void* const* d_in, const int* in_sizes, int n_in,
                              void* d_out, int out_size) {
    const float* x   = (const float*)d_in[0];
    const void*  ei  = d_in[1];
    const float* W1  = (const float*)d_in[2];
    const float* b1  = (const float*)d_in[3];
    const float* W2  = (const float*)d_in[4];
    const float* b2  = (const float*)d_in[5];
    const float* W3  = (const float*)d_in[6];
    const float* b3  = (const float*)d_in[7];
    const float* Wg1 = (const float*)d_in[8];
    const float* bg1 = (const float*)d_in[9];
    const float* Wg2 = (const float*)d_in[10];
    const float* bg2 = (const float*)d_in[11];
    float* out = (float*)d_out;

    int E = in_sizes[1] / 2;
    if (E > EE) E = EE;

    const int TB = 256;
    int gN = (NN + TB - 1) / TB;
    int gE = (E + TB - 1) / TB;

    k_detect<<<1, 1>>>((const long long*)ei);
    k_mlp_front<<<4, TB>>>(x, W1, b1, W2, b2);
    k_deg_init<<<gN, TB>>>();
    k_prep_edges<<<gE, TB>>>(ei, E);
    k_dinv<<<gN, TB>>>();
    k_gemv<<<gN, TB>>>((const float4*)W3, (const float4*)b3, Wg1);
    k_edge1<<<gE, TB>>>(E);
    k_node2<<<gN, TB>>>(bg1, Wg2);
    k_edge2<<<gE, TB>>>(E);
    k_out<<<gN, TB>>>(out, bg2);
}

// round 8
// speedup vs baseline: 1.0803x; 1.0803x over previous
#include <cuda_runtime.h>
#include <math.h>

#define NN 100000
#define EE 3200000

// ---------------- scratch ----------------------------------------------------
__device__ float  g_h2[512];
__device__ float  g_deg[NN];
__device__ float  g_dinv[NN];
__device__ float2 g_ms1[NN];     // m1 * dinv  (gather side of conv1)
__device__ float2 g_agg1[NN];    // conv1 accumulator, init = m1*dinv (self-loop, pre-factored)
__device__ float  g_ms2[NN];
__device__ float  g_agg2[NN];
__device__ int2   g_edge[EE];    // interleaved (src, dst) pairs
__device__ int    g_is64;

// ---------------- fused init: deg=1 | MLP front | dtype detect ---------------
// blocks [0, gN)      : g_deg init
// blocks gN .. gN+3   : h2 = relu(relu(x@W1+b1)@W2+b2)   (128 outputs each)
// block  gN+4         : int64-vs-int32 detection (parallel, 1 round trip)
__global__ void k_init(const float* __restrict__ x,
                       const float* __restrict__ W1,
                       const float* __restrict__ b1,
                       const float* __restrict__ W2,
                       const float* __restrict__ b2,
                       const long long* __restrict__ ei, int gN) {
    int b = blockIdx.x;
    int t = threadIdx.x;

    if (b < gN) {
        int n = b * 256 + t;
        if (n < NN) g_deg[n] = 1.0f;   // +1 self-loop
        return;
    }
    if (b == gN + 4) {
        if (t < 32) {
            long long v = ei[t];
            unsigned bad = __ballot_sync(0xFFFFFFFF, v < 0 || v >= NN);
            if (t == 0) g_is64 = (bad == 0) ? 1 : 0;
        }
        return;
    }

    // MLP blocks
    int mb = b - gN;
    __shared__ float sx[128];
    __shared__ float sh1[256];
    __shared__ float red[256];
    if (t < 128) sx[t] = x[t];
    __syncthreads();

    float acc = 0.f;
    #pragma unroll 8
    for (int k = 0; k < 128; k++) acc = fmaf(sx[k], W1[k * 256 + t], acc);
    sh1[t] = fmaxf(acc + b1[t], 0.f);
    __syncthreads();

    int j = mb * 128 + (t & 127);
    int slice = t >> 7;              // 0 or 1: split-k
    float a2 = 0.f;
    int k0 = slice * 128;
    #pragma unroll 8
    for (int k = k0; k < k0 + 128; k++) a2 = fmaf(sh1[k], W2[k * 512 + j], a2);
    red[t] = a2;
    __syncthreads();
    if (slice == 0) g_h2[j] = fmaxf(red[t] + red[t + 128] + b2[j], 0.f);
}

// ---------------- edge prep: pack to int2 pairs + degree scatter ------------
// 2 edges per thread, vector loads on both dtype paths.
__global__ void k_prep(const void* __restrict__ ei, int E) {
    int e = (blockIdx.x * blockDim.x + threadIdx.x) * 2;
    if (e >= E) return;
    bool two = (e + 1 < E);
    int s0, d0, s1 = 0, d1 = 0;
    if (g_is64) {
        const long long* p = (const long long*)ei;
        if (two) {
            longlong2 sv = *(const longlong2*)(p + e);
            longlong2 dv = *(const longlong2*)(p + E + e);
            s0 = (int)sv.x; s1 = (int)sv.y;
            d0 = (int)dv.x; d1 = (int)dv.y;
        } else {
            s0 = (int)p[e]; d0 = (int)p[E + e];
        }
    } else {
        const int* p = (const int*)ei;
        if (two) {
            int2 sv = *(const int2*)(p + e);
            int2 dv = *(const int2*)(p + E + e);
            s0 = sv.x; s1 = sv.y; d0 = dv.x; d1 = dv.y;
        } else {
            s0 = p[e]; d0 = p[E + e];
        }
    }
    if (two) {
        *(int4*)&g_edge[e] = make_int4(s0, d0, s1, d1);
        atomicAdd(&g_deg[d0], 1.0f);
        atomicAdd(&g_deg[d1], 1.0f);
    } else {
        g_edge[e] = make_int2(s0, d0);
        atomicAdd(&g_deg[d0], 1.0f);
    }
}

// ---------------- BIG GEMV + fused dinv + conv1 prologue --------------------
// One thread per node: float4 over 4 features; W3 fully coalesced.
__global__ void k_gemv(const float4* __restrict__ W3,
                       const float4* __restrict__ b3,
                       const float*  __restrict__ Wg1) {
    __shared__ float sh2[512];
    __shared__ float swg[8];
    int t = threadIdx.x;
    for (int i = t; i < 512; i += 256) sh2[i] = g_h2[i];
    if (t < 8) swg[t] = Wg1[t];
    __syncthreads();

    int n = blockIdx.x * 256 + t;
    if (n >= NN) return;

    float4 acc = b3[n];
    const float4* Wp = W3 + n;
    #pragma unroll 8
    for (int k = 0; k < 512; k++) {
        float4 w = Wp[k * 100000];
        float  h = sh2[k];
        acc.x = fmaf(h, w.x, acc.x);
        acc.y = fmaf(h, w.y, acc.y);
        acc.z = fmaf(h, w.z, acc.z);
        acc.w = fmaf(h, w.w, acc.w);
    }
    float h0 = fmaxf(acc.x, 0.f);
    float h1 = fmaxf(acc.y, 0.f);
    float h2 = fmaxf(acc.z, 0.f);
    float h3 = fmaxf(acc.w, 0.f);

    // m1 = h @ Wg1   (Wg1 row-major [4,2])
    float m0 = h0 * swg[0] + h1 * swg[2] + h2 * swg[4] + h3 * swg[6];
    float m1 = h0 * swg[1] + h1 * swg[3] + h2 * swg[5] + h3 * swg[7];

    float di = rsqrtf(g_deg[n]);
    g_dinv[n] = di;
    float2 v = make_float2(m0 * di, m1 * di);
    g_ms1[n]  = v;
    g_agg1[n] = v;   // self-loop term, pre-factored: final *di gives m/deg
}

// ---------------- conv1 edge scatter: 2 edges/thread, no dinv gather --------
__global__ void k_edge1(int E) {
    int e = (blockIdx.x * blockDim.x + threadIdx.x) * 2;
    if (e >= E) return;
    if (e + 1 < E) {
        int4 ed = *(const int4*)&g_edge[e];
        float2 a = g_ms1[ed.x];
        float2 b = g_ms1[ed.z];
        asm volatile("red.global.add.v2.f32 [%0], {%1, %2};"
                     :: "l"(&g_agg1[ed.y]), "f"(a.x), "f"(a.y) : "memory");
        asm volatile("red.global.add.v2.f32 [%0], {%1, %2};"
                     :: "l"(&g_agg1[ed.w]), "f"(b.x), "f"(b.y) : "memory");
    } else {
        int2 ed = g_edge[e];
        float2 a = g_ms1[ed.x];
        asm volatile("red.global.add.v2.f32 [%0], {%1, %2};"
                     :: "l"(&g_agg1[ed.y]), "f"(a.x), "f"(a.y) : "memory");
    }
}

// ---------------- conv1 epilogue + conv2 prologue ---------------------------
__global__ void k_node2(const float* __restrict__ bg1,
                        const float* __restrict__ Wg2) {
    int n = blockIdx.x * blockDim.x + threadIdx.x;
    if (n >= NN) return;
    float  di = g_dinv[n];
    float2 a  = g_agg1[n];
    float z0 = fmaxf(a.x * di + bg1[0], 0.f);
    float z1 = fmaxf(a.y * di + bg1[1], 0.f);
    float m2 = z0 * Wg2[0] + z1 * Wg2[1];
    g_ms2[n]  = m2 * di;
    g_agg2[n] = m2 * di;   // pre-factored self-loop
}

// ---------------- conv2 edge scatter: 2 edges/thread, no dinv gather --------
__global__ void k_edge2(int E) {
    int e = (blockIdx.x * blockDim.x + threadIdx.x) * 2;
    if (e >= E) return;
    if (e + 1 < E) {
        int4 ed = *(const int4*)&g_edge[e];
        atomicAdd(&g_agg2[ed.y], g_ms2[ed.x]);
        atomicAdd(&g_agg2[ed.w], g_ms2[ed.z]);
    } else {
        int2 ed = g_edge[e];
        atomicAdd(&g_agg2[ed.y], g_ms2[ed.x]);
    }
}

// ---------------- output: sigmoid -------------------------------------------
__global__ void k_out(float* __restrict__ out, const float* __restrict__ bg2) {
    int n = blockIdx.x * blockDim.x + threadIdx.x;
    if (n >= NN) return;
    float v = g_agg2[n] * g_dinv[n] + bg2[0];
    out[n] = 1.0f / (1.0f + expf(-v));
}

// ---------------- launch ----------------------------------------------------
extern "C" void kernel_launch(void* const* d_in, const int* in_sizes, int n_in,
                              void* d_out, int out_size) {
    const float* x   = (const float*)d_in[0];
    const void*  ei  = d_in[1];
    const float* W1  = (const float*)d_in[2];
    const float* b1  = (const float*)d_in[3];
    const float* W2  = (const float*)d_in[4];
    const float* b2  = (const float*)d_in[5];
    const float* W3  = (const float*)d_in[6];
    const float* b3  = (const float*)d_in[7];
    const float* Wg1 = (const float*)d_in[8];
    const float* bg1 = (const float*)d_in[9];
    const float* Wg2 = (const float*)d_in[10];
    const float* bg2 = (const float*)d_in[11];
    float* out = (float*)d_out;

    int E = in_sizes[1] / 2;
    if (E > EE) E = EE;

    const int TB = 256;
    int gN  = (NN + TB - 1) / TB;
    int gE2 = ((E + 1) / 2 + TB - 1) / TB;

    k_init <<<gN + 5, TB>>>(x, W1, b1, W2, b2, (const long long*)ei, gN);
    k_prep <<<gE2, TB>>>(ei, E);
    k_gemv <<<gN, TB>>>((const float4*)W3, (const float4*)b3, Wg1);
    k_edge1<<<gE2, TB>>>(E);
    k_node2<<<gN, TB>>>(bg1, Wg2);
    k_edge2<<<gE2, TB>>>(E);
    k_out  <<<gN, TB>>>(out, bg2);
}

// round 9
// speedup vs baseline: 1.0940x; 1.0127x over previous
#include <cuda_runtime.h>
#include <math.h>

#define NN 100000
#define EE 3200000

// ---------------- scratch ----------------------------------------------------
__device__ float  g_h2[512];
__device__ float  g_deg[NN];     // edge counts (from 0; +1 self-loop added in k_post)
__device__ float  g_dinv[NN];
__device__ float2 g_ms1[NN];     // raw m1 from GEMV, then m1*dinv after k_post
__device__ float2 g_agg1[NN];    // conv1 accumulator, init = m1*dinv (pre-factored)
__device__ float  g_ms2[NN];
__device__ float  g_agg2[NN];
__device__ int2   g_edge[EE];    // interleaved (src, dst)

// ---------------- k_front: MLP (blocks 0..3) + deg zeroing (rest) -----------
__global__ void k_front(const float* __restrict__ x,
                        const float* __restrict__ W1,
                        const float* __restrict__ b1,
                        const float* __restrict__ W2,
                        const float* __restrict__ b2) {
    int b = blockIdx.x;
    int t = threadIdx.x;

    if (b >= 4) {                       // degree zeroing
        int n = (b - 4) * 256 + t;
        if (n < NN) g_deg[n] = 0.0f;
        return;
    }

    __shared__ float sx[128];
    __shared__ float sh1[256];
    __shared__ float red[256];
    if (t < 128) sx[t] = x[t];
    __syncthreads();

    float acc = 0.f;
    #pragma unroll 8
    for (int k = 0; k < 128; k++) acc = fmaf(sx[k], W1[k * 256 + t], acc);
    sh1[t] = fmaxf(acc + b1[t], 0.f);
    __syncthreads();

    int j = b * 128 + (t & 127);
    int slice = t >> 7;                 // 2-way split-k
    float a2 = 0.f;
    int k0 = slice * 128;
    #pragma unroll 8
    for (int k = k0; k < k0 + 128; k++) a2 = fmaf(sh1[k], W2[k * 512 + j], a2);
    red[t] = a2;
    __syncthreads();
    if (slice == 0) g_h2[j] = fmaxf(red[t] + red[t + 128] + b2[j], 0.f);
}

// ---------------- k_big: GEMV blocks [0,gN) + edge-prep blocks [gN, ...) ----
// GEMV path: one thread per node, float4 over features; writes RAW m1.
// Prep path: per-block dtype detect, 4 edges/thread, pack int2 + deg atomics.
__global__ void k_big(const float4* __restrict__ W3,
                      const float4* __restrict__ b3,
                      const float*  __restrict__ Wg1,
                      const void*   __restrict__ ei,
                      int E, int gN) {
    int b = blockIdx.x;
    int t = threadIdx.x;

    if (b < gN) {
        // ---- GEMV main ----
        __shared__ float sh2[512];
        __shared__ float swg[8];
        for (int i = t; i < 512; i += 256) sh2[i] = g_h2[i];
        if (t < 8) swg[t] = Wg1[t];
        __syncthreads();

        int n = b * 256 + t;
        if (n >= NN) return;

        float4 acc = b3[n];
        const float4* Wp = W3 + n;
        #pragma unroll 8
        for (int k = 0; k < 512; k++) {
            float4 w = Wp[k * 100000];
            float  h = sh2[k];
            acc.x = fmaf(h, w.x, acc.x);
            acc.y = fmaf(h, w.y, acc.y);
            acc.z = fmaf(h, w.z, acc.z);
            acc.w = fmaf(h, w.w, acc.w);
        }
        float h0 = fmaxf(acc.x, 0.f);
        float h1 = fmaxf(acc.y, 0.f);
        float h2 = fmaxf(acc.z, 0.f);
        float h3 = fmaxf(acc.w, 0.f);

        float m0 = h0 * swg[0] + h1 * swg[2] + h2 * swg[4] + h3 * swg[6];
        float m1 = h0 * swg[1] + h1 * swg[3] + h2 * swg[5] + h3 * swg[7];
        g_ms1[n] = make_float2(m0, m1);          // raw; k_post applies dinv
        return;
    }

    // ---- edge prep ----
    __shared__ int s_is64;
    if (t < 32) {
        long long v = ((const long long*)ei)[t];
        unsigned bad = __ballot_sync(0xFFFFFFFF, v < 0 || v >= NN);
        if (t == 0) s_is64 = (bad == 0) ? 1 : 0;
    }
    __syncthreads();
    int is64 = s_is64;

    int e = ((b - gN) * 256 + t) * 4;
    if (e >= E) return;

    if (e + 3 < E) {
        int s0, s1, s2, s3, d0, d1, d2, d3;
        if (is64) {
            const long long* p = (const long long*)ei;
            longlong2 sa = *(const longlong2*)(p + e);
            longlong2 sb = *(const longlong2*)(p + e + 2);
            longlong2 da = *(const longlong2*)(p + E + e);
            longlong2 db = *(const longlong2*)(p + E + e + 2);
            s0 = (int)sa.x; s1 = (int)sa.y; s2 = (int)sb.x; s3 = (int)sb.y;
            d0 = (int)da.x; d1 = (int)da.y; d2 = (int)db.x; d3 = (int)db.y;
        } else {
            const int* p = (const int*)ei;
            int4 sv = *(const int4*)(p + e);
            int4 dv = *(const int4*)(p + E + e);
            s0 = sv.x; s1 = sv.y; s2 = sv.z; s3 = sv.w;
            d0 = dv.x; d1 = dv.y; d2 = dv.z; d3 = dv.w;
        }
        *(int4*)&g_edge[e]     = make_int4(s0, d0, s1, d1);
        *(int4*)&g_edge[e + 2] = make_int4(s2, d2, s3, d3);
        atomicAdd(&g_deg[d0], 1.0f);
        atomicAdd(&g_deg[d1], 1.0f);
        atomicAdd(&g_deg[d2], 1.0f);
        atomicAdd(&g_deg[d3], 1.0f);
    } else {
        for (int i = e; i < E; i++) {
            int s, d;
            if (is64) {
                const long long* p = (const long long*)ei;
                s = (int)p[i]; d = (int)p[E + i];
            } else {
                const int* p = (const int*)ei;
                s = p[i]; d = p[E + i];
            }
            g_edge[i] = make_int2(s, d);
            atomicAdd(&g_deg[d], 1.0f);
        }
    }
}

// ---------------- k_post: dinv + scale messages + seed accumulator ----------
__global__ void k_post() {
    int n = blockIdx.x * blockDim.x + threadIdx.x;
    if (n >= NN) return;
    float di = rsqrtf(g_deg[n] + 1.0f);          // +1 self-loop
    g_dinv[n] = di;
    float2 m = g_ms1[n];
    float2 v = make_float2(m.x * di, m.y * di);
    g_ms1[n]  = v;
    g_agg1[n] = v;                               // pre-factored self-loop term
}

// ---------------- conv1 edge scatter: 4 edges/thread ------------------------
__global__ void k_edge1(int E) {
    int e = (blockIdx.x * blockDim.x + threadIdx.x) * 4;
    if (e >= E) return;
    if (e + 3 < E) {
        int4 ea = *(const int4*)&g_edge[e];
        int4 eb = *(const int4*)&g_edge[e + 2];
        float2 a = g_ms1[ea.x];
        float2 b = g_ms1[ea.z];
        float2 c = g_ms1[eb.x];
        float2 d = g_ms1[eb.z];
        asm volatile("red.global.add.v2.f32 [%0], {%1, %2};"
                     :: "l"(&g_agg1[ea.y]), "f"(a.x), "f"(a.y) : "memory");
        asm volatile("red.global.add.v2.f32 [%0], {%1, %2};"
                     :: "l"(&g_agg1[ea.w]), "f"(b.x), "f"(b.y) : "memory");
        asm volatile("red.global.add.v2.f32 [%0], {%1, %2};"
                     :: "l"(&g_agg1[eb.y]), "f"(c.x), "f"(c.y) : "memory");
        asm volatile("red.global.add.v2.f32 [%0], {%1, %2};"
                     :: "l"(&g_agg1[eb.w]), "f"(d.x), "f"(d.y) : "memory");
    } else {
        for (int i = e; i < E; i++) {
            int2 ed = g_edge[i];
            float2 a = g_ms1[ed.x];
            asm volatile("red.global.add.v2.f32 [%0], {%1, %2};"
                         :: "l"(&g_agg1[ed.y]), "f"(a.x), "f"(a.y) : "memory");
        }
    }
}

// ---------------- conv1 epilogue + conv2 prologue ---------------------------
__global__ void k_node2(const float* __restrict__ bg1,
                        const float* __restrict__ Wg2) {
    int n = blockIdx.x * blockDim.x + threadIdx.x;
    if (n >= NN) return;
    float  di = g_dinv[n];
    float2 a  = g_agg1[n];
    float z0 = fmaxf(a.x * di + bg1[0], 0.f);
    float z1 = fmaxf(a.y * di + bg1[1], 0.f);
    float m2 = z0 * Wg2[0] + z1 * Wg2[1];
    g_ms2[n]  = m2 * di;
    g_agg2[n] = m2 * di;                         // pre-factored self-loop
}

// ---------------- conv2 edge scatter: 4 edges/thread ------------------------
__global__ void k_edge2(int E) {
    int e = (blockIdx.x * blockDim.x + threadIdx.x) * 4;
    if (e >= E) return;
    if (e + 3 < E) {
        int4 ea = *(const int4*)&g_edge[e];
        int4 eb = *(const int4*)&g_edge[e + 2];
        float a = g_ms2[ea.x];
        float b = g_ms2[ea.z];
        float c = g_ms2[eb.x];
        float d = g_ms2[eb.z];
        atomicAdd(&g_agg2[ea.y], a);
        atomicAdd(&g_agg2[ea.w], b);
        atomicAdd(&g_agg2[eb.y], c);
        atomicAdd(&g_agg2[eb.w], d);
    } else {
        for (int i = e; i < E; i++) {
            int2 ed = g_edge[i];
            atomicAdd(&g_agg2[ed.y], g_ms2[ed.x]);
        }
    }
}

// ---------------- output: sigmoid -------------------------------------------
__global__ void k_out(float* __restrict__ out, const float* __restrict__ bg2) {
    int n = blockIdx.x * blockDim.x + threadIdx.x;
    if (n >= NN) return;
    float v = g_agg2[n] * g_dinv[n] + bg2[0];
    out[n] = 1.0f / (1.0f + expf(-v));
}

// ---------------- launch ----------------------------------------------------
extern "C" void kernel_launch(void* const* d_in, const int* in_sizes, int n_in,
                              void* d_out, int out_size) {
    const float* x   = (const float*)d_in[0];
    const void*  ei  = d_in[1];
    const float* W1  = (const float*)d_in[2];
    const float* b1  = (const float*)d_in[3];
    const float* W2  = (const float*)d_in[4];
    const float* b2  = (const float*)d_in[5];
    const float* W3  = (const float*)d_in[6];
    const float* b3  = (const float*)d_in[7];
    const float* Wg1 = (const float*)d_in[8];
    const float* bg1 = (const float*)d_in[9];
    const float* Wg2 = (const float*)d_in[10];
    const float* bg2 = (const float*)d_in[11];
    float* out = (float*)d_out;

    int E = in_sizes[1] / 2;
    if (E > EE) E = EE;

    const int TB = 256;
    int gN  = (NN + TB - 1) / TB;                    // 391
    int gE4 = ((E + 3) / 4 + TB - 1) / TB;           // 3125 for E=3.2M

    k_front<<<gN + 4, TB>>>(x, W1, b1, W2, b2);
    k_big  <<<gN + gE4, TB>>>((const float4*)W3, (const float4*)b3, Wg1, ei, E, gN);
    k_post <<<gN, TB>>>();
    k_edge1<<<gE4, TB>>>(E);
    k_node2<<<gN, TB>>>(bg1, Wg2);
    k_edge2<<<gE4, TB>>>(E);
    k_out  <<<gN, TB>>>(out, bg2);
}

// round 10
// speedup vs baseline: 1.1240x; 1.0274x over previous
#include <cuda_runtime.h>
#include <math.h>

#define NN 100000
#define EE 3200000
#define TB 256
#define GN ((NN + TB - 1) / TB)    // 391 node blocks

// ---------------- scratch ----------------------------------------------------
__device__ float  g_h2[512];
__device__ float  g_deg[NN];       // edge counts (zeroed each call)
__device__ float  g_dinv[NN];
__device__ float2 g_ms1[NN];       // raw m1 from GEMV, scaled by dinv in post phase
__device__ float2 g_agg1[NN];      // conv1 accumulator (pre-factored self-loop seed)
__device__ float  g_ms2[NN];
__device__ float  g_agg2[NN];
__device__ int2   g_edge[EE];      // interleaved (src,dst)

// phase flags (reset by k_out each call; zero-init at load)
__device__ volatile unsigned g_f_mlp;
__device__ volatile unsigned g_f_zero;
__device__ volatile unsigned g_f_post;
__device__ volatile unsigned g_f_node2;

__device__ __forceinline__ void block_release(volatile unsigned* f) {
    __syncthreads();
    if (threadIdx.x == 0) { __threadfence(); atomicAdd((unsigned*)f, 1u); }
}
__device__ __forceinline__ void block_wait(volatile unsigned* f, unsigned tgt) {
    if (threadIdx.x == 0) { while (*f < tgt) __nanosleep(200); }
    __syncthreads();
}

// ---------------- k_big: MLP | deg-zero | GEMV | edge-prep, one launch -------
// bids [0,4)          MLP front (releases g_f_mlp)
// bids [4,4+GN)       deg zeroing (releases g_f_zero)
// bids [4+GN,4+2GN)   GEMV (waits g_f_mlp)
// bids [4+2GN,...)    edge prep (waits g_f_zero)
__global__ void k_big(const float*  __restrict__ x,
                      const float*  __restrict__ W1,
                      const float*  __restrict__ b1,
                      const float*  __restrict__ W2,
                      const float*  __restrict__ b2,
                      const float4* __restrict__ W3,
                      const float4* __restrict__ b3,
                      const float*  __restrict__ Wg1,
                      const void*   __restrict__ ei, int E) {
    int b = blockIdx.x;
    int t = threadIdx.x;

    if (b < 4) {
        // ---- MLP: h2 = relu(relu(x@W1+b1)@W2+b2), 128 outputs per block ----
        __shared__ float sx[128];
        __shared__ float sh1[256];
        __shared__ float red[256];
        if (t < 128) sx[t] = x[t];
        __syncthreads();

        float acc = 0.f;
        #pragma unroll 8
        for (int k = 0; k < 128; k++) acc = fmaf(sx[k], W1[k * 256 + t], acc);
        sh1[t] = fmaxf(acc + b1[t], 0.f);
        __syncthreads();

        int j = b * 128 + (t & 127);
        int slice = t >> 7;
        float a2 = 0.f;
        int k0 = slice * 128;
        #pragma unroll 8
        for (int k = k0; k < k0 + 128; k++) a2 = fmaf(sh1[k], W2[k * 512 + j], a2);
        red[t] = a2;
        __syncthreads();
        if (slice == 0) g_h2[j] = fmaxf(red[t] + red[t + 128] + b2[j], 0.f);
        block_release(&g_f_mlp);
        return;
    }

    if (b < 4 + GN) {
        // ---- degree zeroing ----
        int n = (b - 4) * TB + t;
        if (n < NN) g_deg[n] = 0.0f;
        block_release(&g_f_zero);
        return;
    }

    if (b < 4 + 2 * GN) {
        // ---- GEMV: one thread per node, float4 over 4 features ----
        __shared__ float sh2[512];
        __shared__ float swg[8];
        int n = (b - 4 - GN) * TB + t;

        float4 acc = make_float4(0.f, 0.f, 0.f, 0.f);
        if (n < NN) acc = __ldcs(b3 + n);        // prefetch before wait

        if (t < 8) swg[t] = Wg1[t];
        block_wait(&g_f_mlp, 4);
        for (int i = t; i < 512; i += TB) sh2[i] = g_h2[i];
        __syncthreads();

        if (n >= NN) return;
        const float4* Wp = W3 + n;
        #pragma unroll 8
        for (int k = 0; k < 512; k++) {
            float4 w = __ldcs(Wp + k * 100000);
            float  h = sh2[k];
            acc.x = fmaf(h, w.x, acc.x);
            acc.y = fmaf(h, w.y, acc.y);
            acc.z = fmaf(h, w.z, acc.z);
            acc.w = fmaf(h, w.w, acc.w);
        }
        float h0 = fmaxf(acc.x, 0.f);
        float h1 = fmaxf(acc.y, 0.f);
        float h2 = fmaxf(acc.z, 0.f);
        float h3 = fmaxf(acc.w, 0.f);

        float m0 = h0 * swg[0] + h1 * swg[2] + h2 * swg[4] + h3 * swg[6];
        float m1 = h0 * swg[1] + h1 * swg[3] + h2 * swg[5] + h3 * swg[7];
        g_ms1[n] = make_float2(m0, m1);          // raw; post phase applies dinv
        return;
    }

    // ---- edge prep: dtype detect, pack int2, degree atomics ----
    __shared__ int s_is64;
    if (t < 32) {
        long long v = __ldcs(((const long long*)ei) + t);
        unsigned bad = __ballot_sync(0xFFFFFFFF, v < 0 || v >= NN);
        if (t == 0) s_is64 = (bad == 0) ? 1 : 0;
    }
    block_wait(&g_f_zero, GN);
    int is64 = s_is64;

    int e = ((b - 4 - 2 * GN) * TB + t) * 4;
    if (e >= E) return;

    if (e + 3 < E) {
        int s0, s1, s2, s3, d0, d1, d2, d3;
        if (is64) {
            const long long* p = (const long long*)ei;
            longlong2 sa = __ldcs((const longlong2*)(p + e));
            longlong2 sb = __ldcs((const longlong2*)(p + e + 2));
            longlong2 da = __ldcs((const longlong2*)(p + E + e));
            longlong2 db = __ldcs((const longlong2*)(p + E + e + 2));
            s0 = (int)sa.x; s1 = (int)sa.y; s2 = (int)sb.x; s3 = (int)sb.y;
            d0 = (int)da.x; d1 = (int)da.y; d2 = (int)db.x; d3 = (int)db.y;
        } else {
            const int* p = (const int*)ei;
            int4 sv = __ldcs((const int4*)(p + e));
            int4 dv = __ldcs((const int4*)(p + E + e));
            s0 = sv.x; s1 = sv.y; s2 = sv.z; s3 = sv.w;
            d0 = dv.x; d1 = dv.y; d2 = dv.z; d3 = dv.w;
        }
        __stcs((int4*)&g_edge[e],     make_int4(s0, d0, s1, d1));
        __stcs((int4*)&g_edge[e + 2], make_int4(s2, d2, s3, d3));
        atomicAdd(&g_deg[d0], 1.0f);
        atomicAdd(&g_deg[d1], 1.0f);
        atomicAdd(&g_deg[d2], 1.0f);
        atomicAdd(&g_deg[d3], 1.0f);
    } else {
        for (int i = e; i < E; i++) {
            int s, d;
            if (is64) {
                const long long* p = (const long long*)ei;
                s = (int)p[i]; d = (int)p[E + i];
            } else {
                const int* p = (const int*)ei;
                s = p[i]; d = p[E + i];
            }
            g_edge[i] = make_int2(s, d);
            atomicAdd(&g_deg[d], 1.0f);
        }
    }
}

// ---------------- k_e1: post phase (bids [0,GN)) + conv1 edge scatter -------
__global__ void k_e1(int E) {
    int b = blockIdx.x;
    int t = threadIdx.x;

    if (b < GN) {
        int n = b * TB + t;
        if (n < NN) {
            float di = rsqrtf(g_deg[n] + 1.0f);  // +1 self-loop
            g_dinv[n] = di;
            float2 m = g_ms1[n];
            float2 v = make_float2(m.x * di, m.y * di);
            g_ms1[n]  = v;
            g_agg1[n] = v;                       // pre-factored self-loop seed
        }
        block_release(&g_f_post);
        return;
    }
    block_wait(&g_f_post, GN);

    int e = ((b - GN) * TB + t) * 4;
    if (e >= E) return;
    if (e + 3 < E) {
        int4 ea = __ldcs((const int4*)&g_edge[e]);
        int4 eb = __ldcs((const int4*)&g_edge[e + 2]);
        float2 a = g_ms1[ea.x];
        float2 c = g_ms1[ea.z];
        float2 d = g_ms1[eb.x];
        float2 f = g_ms1[eb.z];
        asm volatile("red.global.add.v2.f32 [%0], {%1, %2};"
                     :: "l"(&g_agg1[ea.y]), "f"(a.x), "f"(a.y) : "memory");
        asm volatile("red.global.add.v2.f32 [%0], {%1, %2};"
                     :: "l"(&g_agg1[ea.w]), "f"(c.x), "f"(c.y) : "memory");
        asm volatile("red.global.add.v2.f32 [%0], {%1, %2};"
                     :: "l"(&g_agg1[eb.y]), "f"(d.x), "f"(d.y) : "memory");
        asm volatile("red.global.add.v2.f32 [%0], {%1, %2};"
                     :: "l"(&g_agg1[eb.w]), "f"(f.x), "f"(f.y) : "memory");
    } else {
        for (int i = e; i < E; i++) {
            int2 ed = g_edge[i];
            float2 a = g_ms1[ed.x];
            asm volatile("red.global.add.v2.f32 [%0], {%1, %2};"
                         :: "l"(&g_agg1[ed.y]), "f"(a.x), "f"(a.y) : "memory");
        }
    }
}

// ---------------- k_e2: node2 phase (bids [0,GN)) + conv2 edge scatter ------
__global__ void k_e2(const float* __restrict__ bg1,
                     const float* __restrict__ Wg2, int E) {
    int b = blockIdx.x;
    int t = threadIdx.x;

    if (b < GN) {
        int n = b * TB + t;
        if (n < NN) {
            float  di = g_dinv[n];
            float2 a  = g_agg1[n];
            float z0 = fmaxf(a.x * di + bg1[0], 0.f);
            float z1 = fmaxf(a.y * di + bg1[1], 0.f);
            float m2 = z0 * Wg2[0] + z1 * Wg2[1];
            g_ms2[n]  = m2 * di;
            g_agg2[n] = m2 * di;                 // pre-factored self-loop seed
        }
        block_release(&g_f_node2);
        return;
    }
    block_wait(&g_f_node2, GN);

    int e = ((b - GN) * TB + t) * 4;
    if (e >= E) return;
    if (e + 3 < E) {
        int4 ea = __ldcs((const int4*)&g_edge[e]);
        int4 eb = __ldcs((const int4*)&g_edge[e + 2]);
        float a = g_ms2[ea.x];
        float c = g_ms2[ea.z];
        float d = g_ms2[eb.x];
        float f = g_ms2[eb.z];
        atomicAdd(&g_agg2[ea.y], a);
        atomicAdd(&g_agg2[ea.w], c);
        atomicAdd(&g_agg2[eb.y], d);
        atomicAdd(&g_agg2[eb.w], f);
    } else {
        for (int i = e; i < E; i++) {
            int2 ed = g_edge[i];
            atomicAdd(&g_agg2[ed.y], g_ms2[ed.x]);
        }
    }
}

// ---------------- k_out: sigmoid + flag reset for next replay ---------------
__global__ void k_out(float* __restrict__ out, const float* __restrict__ bg2) {
    if (blockIdx.x == 0 && threadIdx.x == 0) {
        g_f_mlp = 0; g_f_zero = 0; g_f_post = 0; g_f_node2 = 0;
    }
    int n = blockIdx.x * blockDim.x + threadIdx.x;
    if (n >= NN) return;
    float v = g_agg2[n] * g_dinv[n] + bg2[0];
    out[n] = 1.0f / (1.0f + expf(-v));
}

// ---------------- launch ----------------------------------------------------
extern "C" void kernel_launch(void* const* d_in, const int* in_sizes, int n_in,
                              void* d_out, int out_size) {
    const float* x   = (const float*)d_in[0];
    const void*  ei  = d_in[1];
    const float* W1  = (const float*)d_in[2];
    const float* b1  = (const float*)d_in[3];
    const float* W2  = (const float*)d_in[4];
    const float* b2  = (const float*)d_in[5];
    const float* W3  = (const float*)d_in[6];
    const float* b3  = (const float*)d_in[7];
    const float* Wg1 = (const float*)d_in[8];
    const float* bg1 = (const float*)d_in[9];
    const float* Wg2 = (const float*)d_in[10];
    const float* bg2 = (const float*)d_in[11];
    float* out = (float*)d_out;

    int E = in_sizes[1] / 2;
    if (E > EE) E = EE;

    int gE4 = ((E + 3) / 4 + TB - 1) / TB;       // 3125 for E=3.2M

    k_big<<<4 + 2 * GN + gE4, TB>>>(x, W1, b1, W2, b2,
                                    (const float4*)W3, (const float4*)b3,
                                    Wg1, ei, E);
    k_e1 <<<GN + gE4, TB>>>(E);
    k_e2 <<<GN + gE4, TB>>>(bg1, Wg2, E);
    k_out<<<GN, TB>>>(out, bg2);
}